// round 17
// baseline (speedup 1.0000x reference)
#include <cuda_runtime.h>

// Piecewise-linear log-sigmoid approximation (table interp).
// inputs: vals[64*2048*2048] f32, x[65] f32 (uniform linspace), y[65] f32
// output: f32 same shape.
//
// Semantics (matches jax reference):
//   v <  x[0]  -> v
//   v >= x[64] -> 0
//   else out = y[i] + (v - x[i]) * slope[i],  i = floor((v-x0)/h) clamped
//
// Contiguous-slab-per-CTA ordering: each block owns one contiguous slab of
// the array and streams it linearly (best DRAM page locality), with a
// software-pipelined double buffer (prefetch iter i+1 before storing iter i)
// and a peeled final iteration (no redundant prefetch traffic).

#define NBP  65
#define NSEG 64
#define ILP  4
#define THREADS 256
#define BLOCKS  4096
// n4 = 2^26 float4s; slab per block = 2^26/4096 = 16384 float4 (256 KB);
// per-iter per-block = 256*4 = 1024 float4 -> exactly 16 iterations.

__device__ __forceinline__ void compute_store(
        float4* __restrict__ out4, unsigned int base,
        const float4 (&cur)[ILP],
        const float2* __restrict__ coef,
        float x0, float xlast, float invh)
{
    #pragma unroll
    for (int j = 0; j < ILP; j++) {
        float vv[4] = {cur[j].x, cur[j].y, cur[j].z, cur[j].w};
        float oo[4];
        #pragma unroll
        for (int k = 0; k < 4; k++) {
            float val = vv[k];
            int idx = (int)((val - x0) * invh);
            idx = max(0, min(idx, NSEG - 1));
            float2 c = coef[idx];
            float r = fmaf(c.y, val, c.x);
            r = (val <  x0)    ? val  : r;
            r = (val >= xlast) ? 0.0f : r;
            oo[k] = r;
        }
        float4 o;
        o.x = oo[0]; o.y = oo[1]; o.z = oo[2]; o.w = oo[3];
        __stcs(&out4[base + j * THREADS], o);
    }
}

__global__ __launch_bounds__(THREADS) void logsig_kernel(
        const float* __restrict__ vals,
        const float* __restrict__ xs,
        const float* __restrict__ ys,
        float* __restrict__ out,
        unsigned int slab,    // float4s per block (contiguous)
        unsigned int niter)   // slab / (THREADS*ILP), >= 1
{
    // Per-segment affine coefficients: r = c.x + c.y * v
    __shared__ float2 coef[NSEG];
    __shared__ float s_x0, s_xlast, s_invh;

    const unsigned int t = threadIdx.x;
    if (t < NSEG) {
        float x0 = xs[t];
        float x1 = xs[t + 1];
        float y0 = ys[t];
        float y1 = ys[t + 1];
        float slope = (y1 - y0) / (x1 - x0);
        coef[t] = make_float2(fmaf(-x0, slope, y0), slope);
    }
    if (t == 0) {
        float a = xs[0];
        float b = xs[NBP - 1];
        s_x0    = a;
        s_xlast = b;
        s_invh  = (float)NSEG / (b - a);
    }
    __syncthreads();

    const float x0    = s_x0;
    const float xlast = s_xlast;
    const float invh  = s_invh;

    const float4* __restrict__ in4  = reinterpret_cast<const float4*>(vals);
    float4* __restrict__       out4 = reinterpret_cast<float4*>(out);

    const unsigned int step = THREADS * ILP;          // float4s per block-iter
    unsigned int base = blockIdx.x * slab + t;        // linear slab walk

    // Prologue: load iteration 0
    float4 cur[ILP];
    #pragma unroll
    for (int j = 0; j < ILP; j++)
        cur[j] = __ldcs(&in4[base + j * THREADS]);

    // Steady state: prefetch next chunk, then compute+store current.
    for (unsigned int it = 0; it + 1 < niter; it++) {
        unsigned int nbase = base + step;

        float4 nxt[ILP];
        #pragma unroll
        for (int j = 0; j < ILP; j++)
            nxt[j] = __ldcs(&in4[nbase + j * THREADS]);

        compute_store(out4, base, cur, coef, x0, xlast, invh);

        #pragma unroll
        for (int j = 0; j < ILP; j++)
            cur[j] = nxt[j];
        base = nbase;
    }

    // Epilogue: last iteration, no prefetch.
    compute_store(out4, base, cur, coef, x0, xlast, invh);
}

extern "C" void kernel_launch(void* const* d_in, const int* in_sizes, int n_in,
                              void* d_out, int out_size)
{
    const float* vals = (const float*)d_in[0];
    const float* xs   = (const float*)d_in[1];
    const float* ys   = (const float*)d_in[2];
    float* out        = (float*)d_out;

    unsigned int n4    = (unsigned int)(out_size / 4);   // 2^26 float4s
    unsigned int slab  = n4 / BLOCKS;                    // 16384 (divides exactly)
    unsigned int niter = slab / (THREADS * ILP);         // 16

    logsig_kernel<<<BLOCKS, THREADS>>>(vals, xs, ys, out, slab, niter);
}